// round 10
// baseline (speedup 1.0000x reference)
#include <cuda_runtime.h>
#include <cstdint>

#define H      16384
#define BATCH  512
#define INSZ   2048
#define KSEL   64
#define DECAY  0.95f

#define NTH    1024
#define VPT    16          // H / NTH
#define CAP    1024

__device__ float g_enc[(size_t)BATCH * H];   // 32 MB scratch (no-alloc rule)

// ---------------------------------------------------------------------------
__global__ void zero_out_kernel(float4* __restrict__ out, int n4) {
    int i = blockIdx.x * blockDim.x + threadIdx.x;
    if (i < n4) out[i] = make_float4(0.f, 0.f, 0.f, 0.f);
}

// ---------------------------------------------------------------------------
// fp32 GEMM  C[m][n] = sum_k A[m][k] * W[n][k]; 128x128 tile, BK=16
// ---------------------------------------------------------------------------
#define GBM 128
#define GBN 128
#define GBK 16

__global__ void __launch_bounds__(256) sgemm_nt_kernel(
    const float* __restrict__ A, const float* __restrict__ W)
{
    __shared__ float As[GBK][GBM];
    __shared__ float Bs[GBK][GBN];

    const int bn = blockIdx.x * GBN, bm = blockIdx.y * GBM;
    const int tid = threadIdx.x, tx = tid & 15, ty = tid >> 4;

    float acc[8][8];
#pragma unroll
    for (int i = 0; i < 8; i++)
#pragma unroll
        for (int j = 0; j < 8; j++) acc[i][j] = 0.f;

    for (int k0 = 0; k0 < INSZ; k0 += GBK) {
#pragma unroll
        for (int l = 0; l < 2; l++) {
            int q = tid + 256 * l, row = q >> 2, kk = (q & 3) * 4;
            float4 v = *(const float4*)&A[(bm + row) * INSZ + k0 + kk];
            As[kk][row] = v.x; As[kk + 1][row] = v.y;
            As[kk + 2][row] = v.z; As[kk + 3][row] = v.w;
        }
#pragma unroll
        for (int l = 0; l < 2; l++) {
            int q = tid + 256 * l, row = q >> 2, kk = (q & 3) * 4;
            float4 v = *(const float4*)&W[(bn + row) * INSZ + k0 + kk];
            Bs[kk][row] = v.x; Bs[kk + 1][row] = v.y;
            Bs[kk + 2][row] = v.z; Bs[kk + 3][row] = v.w;
        }
        __syncthreads();
#pragma unroll
        for (int k = 0; k < GBK; k++) {
            float a[8], b[8];
#pragma unroll
            for (int i = 0; i < 8; i++) a[i] = As[k][ty * 8 + i];
#pragma unroll
            for (int i = 0; i < 8; i++) b[i] = Bs[k][tx * 8 + i];
#pragma unroll
            for (int i = 0; i < 8; i++)
#pragma unroll
                for (int j = 0; j < 8; j++)
                    acc[i][j] = fmaf(a[i], b[j], acc[i][j]);
        }
        __syncthreads();
    }
#pragma unroll
    for (int i = 0; i < 8; i++) {
        int m = bm + ty * 8 + i;
#pragma unroll
        for (int j = 0; j < 8; j += 4)
            *(float4*)&g_enc[(size_t)m * H + bn + tx * 8 + j] =
                make_float4(acc[i][j], acc[i][j+1], acc[i][j+2], acc[i][j+3]);
    }
}

// ---------------------------------------------------------------------------
// Persistent single-CTA scan.  Final-mask fill order (total-order top_k,
// -0.0 < +0.0): selected positives, then non-selected enc>0 ascending,
// then non-selected enc<0 ascending.
// ---------------------------------------------------------------------------
__global__ void __launch_bounds__(NTH, 1) scan_kernel(float* __restrict__ out)
{
    __shared__ unsigned long long s_ckey[CAP];     // (val_bits<<32)|~idx
    __shared__ unsigned long long s_selkey[KSEL];
    __shared__ unsigned s_selbit[H / 32];          // 512 words
    __shared__ int   s_cnt, s_p;
    __shared__ float s_T;
    __shared__ float s_red[32];
    __shared__ int   s_wcnt[32];

    const int t = threadIdx.x, lane = t & 31, wp = t >> 5;

    float inhib[VPT];
#pragma unroll
    for (int j = 0; j < VPT; j++) inhib[j] = 0.f;
    if (t == 0) s_T = -1.f;

    for (int row = 0; row < BATCH; row++) {
        const float* erow = g_enc + (size_t)row * H;

        // refracted + block max
        float r[VPT];
        float rmax = 0.f;
#pragma unroll
        for (int j = 0; j < VPT; j++) {
            float e = __ldg(erow + t + NTH * j);
            r[j] = fabsf(e) * (1.0f - inhib[j]);
            rmax = fmaxf(rmax, r[j]);
        }
#pragma unroll
        for (int o = 16; o > 0; o >>= 1)
            rmax = fmaxf(rmax, __shfl_xor_sync(0xffffffffu, rmax, o));
        if (lane == 0) s_red[wp] = rmax;
        if (t < H / 32) s_selbit[t] = 0u;          // clear bitmap
        __syncthreads();
        if (t < 32) {
            float v = s_red[t];
#pragma unroll
            for (int o = 16; o > 0; o >>= 1)
                v = fmaxf(v, __shfl_xor_sync(0xffffffffu, v, o));
            if (t == 0) s_red[0] = v;
        }
        __syncthreads();
        rmax = s_red[0];

        float T = s_T;
        if (!(T > 0.f && T < rmax)) T = 0.5f * rmax;
        float Tlo = 0.f, Thi = rmax;
        int M;

        // candidate gather + bisection retry
        for (;;) {
            __syncthreads();
            if (t == 0) s_cnt = 0;
            __syncthreads();
#pragma unroll
            for (int j = 0; j < VPT; j++) {
                bool pred = r[j] > T;
                unsigned bal = __ballot_sync(0xffffffffu, pred);
                if (bal) {
                    int ldr = __ffs(bal) - 1;
                    int base = 0;
                    if (lane == ldr) base = atomicAdd(&s_cnt, __popc(bal));
                    base = __shfl_sync(0xffffffffu, base, ldr);
                    if (pred) {
                        int pos = base + __popc(bal & ((1u << lane) - 1u));
                        if (pos < CAP) {
                            unsigned idx = (unsigned)(t + NTH * j);
                            s_ckey[pos] =
                                ((unsigned long long)__float_as_uint(r[j]) << 32)
                                | (unsigned)(~idx);
                        }
                    }
                }
            }
            __syncthreads();
            M = s_cnt;
            if (M >= KSEL && M <= CAP) break;
            if (M > CAP) Tlo = T; else Thi = T;
            T = 0.5f * (Tlo + Thi);
        }

        // exact rank selection
        if (t == 0) s_p = 0;
        if (t < M) {
            unsigned long long k = s_ckey[t];
            int rank = 0;
            for (int d = 0; d < M; d++) rank += (s_ckey[d] > k);
            if (rank < KSEL) s_selkey[rank] = k;
        }
        __syncthreads();

        // bitmap + inhibition update + positive-selected outputs
        if (t < KSEL) {
            unsigned idx = ~(unsigned)(s_selkey[t]);
            atomicOr(&s_selbit[idx >> 5], 1u << (idx & 31));
        }
#pragma unroll
        for (int j = 0; j < VPT; j++) inhib[j] *= DECAY;
        for (int s = 0; s < KSEL; s++) {
            unsigned idx = ~(unsigned)(s_selkey[s]);
            if ((idx & (NTH - 1)) == (unsigned)t) {
                inhib[idx >> 10] += 1.0f;
                if (__ldg(erow + idx) > 0.f) {
                    out[(size_t)row * H + idx] = 1.0f;
                    atomicAdd(&s_p, 1);
                }
            }
        }
        __syncthreads();
        int cnt = s_p;                 // same value on all threads
        __syncthreads();

        // streaming fill: pass 0 = +0.0 group (enc>0), pass 1 = -0.0 (enc<0)
        for (int pass = 0; pass < 2 && cnt < KSEL; pass++) {
            for (int base = 0; base < H; base += NTH) {
                int idx = base + t;
                bool sel = (s_selbit[idx >> 5] >> (idx & 31)) & 1u;
                float e = __ldg(erow + idx);
                bool cand = !sel && (pass == 0 ? (e > 0.f) : (e < 0.f));
                unsigned bal = __ballot_sync(0xffffffffu, cand);
                if (lane == 0) s_wcnt[wp] = __popc(bal);
                __syncthreads();
                int pre = 0, tot = 0;
#pragma unroll
                for (int w = 0; w < 32; w++) {
                    int c = s_wcnt[w];
                    if (w < wp) pre += c;
                    tot += c;
                }
                pre += __popc(bal & ((1u << lane) - 1u));
                if (cand && cnt + pre < KSEL)
                    out[(size_t)row * H + idx] = 1.0f;
                cnt += tot;            // uniform across block
                __syncthreads();       // s_wcnt reuse guard
                if (cnt >= KSEL) break;
            }
        }

        // warm-start threshold for next row
        if (t == 0)
            s_T = __uint_as_float((unsigned)(s_selkey[KSEL - 1] >> 32)) * 0.85f;
        __syncthreads();
    }
}

// ---------------------------------------------------------------------------
extern "C" void kernel_launch(void* const* d_in, const int* in_sizes, int n_in,
                              void* d_out, int out_size)
{
    const float* inputs = (const float*)d_in[0];   // [512, 2048]
    const float* W      = (const float*)d_in[1];   // [16384, 2048]
    float* out          = (float*)d_out;           // [512, 16384]

    const int n4 = (BATCH * H) / 4;
    zero_out_kernel<<<(n4 + 255) / 256, 256>>>((float4*)out, n4);

    dim3 ggrid(H / GBN, BATCH / GBM);              // (128, 4)
    sgemm_nt_kernel<<<ggrid, 256>>>(inputs, W);

    scan_kernel<<<1, NTH>>>(out);
}